// round 12
// baseline (speedup 1.0000x reference)
#include <cuda_runtime.h>
#include <math.h>

#define Bdim 4
#define Sdim 512
#define Kdim 32
#define Vdim 32000
#define ROWS (Bdim * Sdim)   /* 2048 */
#define NTHREADS 256
#define NBLOCKS 1024         /* single full wave: each CTA does 2 rows */
#define V4 (Vdim / 4)        /* 8000 */
#define CAND_CAP 1024
#define BATCH_END 7168       /* 7 * NTHREADS * 4; tail = 832 float4s */

__device__ __forceinline__ float warp_sum(float v) {
#pragma unroll
    for (int o = 16; o > 0; o >>= 1) v += __shfl_xor_sync(0xffffffffu, v, o);
    return v;
}
__device__ __forceinline__ float warp_max(float v) {
#pragma unroll
    for (int o = 16; o > 0; o >>= 1) v = fmaxf(v, __shfl_xor_sync(0xffffffffu, v, o));
    return v;
}
__device__ __forceinline__ float max4(float4 v) {
    return fmaxf(fmaxf(v.x, v.y), fmaxf(v.z, v.w));
}
// fallback-only: insert into descending 8-list
__device__ __forceinline__ void ins8(float (&t)[8], float v) {
    if (v <= t[7]) return;
    t[7] = v;
#pragma unroll
    for (int i = 7; i > 0; --i)
        if (t[i] > t[i - 1]) { float tmp = t[i - 1]; t[i - 1] = t[i]; t[i] = tmp; }
}
// rare hit path: ONE atomic per hit lane, then sequential stores
__device__ __forceinline__ void collect(float4 v, float T, float* s_cand, int* s_cnt_c) {
    int n = (v.x >= T) + (v.y >= T) + (v.z >= T) + (v.w >= T);
    int p = atomicAdd(s_cnt_c, n);
    if (v.x >= T) { if (p < CAND_CAP) s_cand[p] = v.x; p++; }
    if (v.y >= T) { if (p < CAND_CAP) s_cand[p] = v.y; p++; }
    if (v.z >= T) { if (p < CAND_CAP) s_cand[p] = v.z; p++; }
    if (v.w >= T) { if (p < CAND_CAP) s_cand[p] = v.w; p++; }
}

__global__ __launch_bounds__(NTHREADS, 8)   /* cap regs at 32 -> 8 CTAs/SM */
void robust_combiner_kernel(const int*   __restrict__ tgt,
                            const float* __restrict__ dists,
                            const float* __restrict__ keyf,
                            const float* __restrict__ nprobs,
                            const float* __restrict__ selp,
                            const float* __restrict__ Wf,  const float* __restrict__ bf,
                            const float* __restrict__ W1a, const float* __restrict__ b1a,
                            const float* __restrict__ W1b, const float* __restrict__ b1b,
                            const float* __restrict__ W2a, const float* __restrict__ b2a,
                            const float* __restrict__ W2b, const float* __restrict__ b2b,
                            float* __restrict__ out)
{
    const int tid = threadIdx.x;

    __shared__ float s_max[NTHREADS];
    __shared__ float s_cand[CAND_CAP];
    __shared__ int   s_cnt_c;
    __shared__ float s_T;
    __shared__ float s_top8[8];
    __shared__ float s_d[Kdim], s_lk[Kdim], s_ls[Kdim], s_cnt[Kdim], s_p[Kdim];
    __shared__ int   s_t[Kdim];

    const float4 z4 = make_float4(0.f, 0.f, 0.f, 0.f);

#pragma unroll 1
    for (int rr = 0; rr < 2; rr++) {
        const int row = blockIdx.x + rr * NBLOCKS;

        const float4* __restrict__ in4  = reinterpret_cast<const float4*>(nprobs) + (size_t)row * V4;
        float4*       __restrict__ out4 = reinterpret_cast<float4*>(out)          + (size_t)row * V4;
        const size_t kbase = (size_t)row * Kdim;

        if (tid == 0) s_cnt_c = 0;

        // ---- Phase 0: 4096-element subset sample (4 float4 / thread) ----
        {
            float4 a = in4[tid];
            float4 b = in4[tid + NTHREADS];
            float4 c = in4[tid + 2 * NTHREADS];
            float4 d = in4[tid + 3 * NTHREADS];
            s_max[tid] = fmaxf(fmaxf(max4(a), max4(b)), fmaxf(max4(c), max4(d)));
        }
        __syncthreads();

        // ---- Concurrent: warp 0 threshold; warps 1-4 prefetch phase-C inputs ----
        if (tid < 32) {
            // T = 8th-largest of 256 thread maxima (each a real row element)
            // -> >= 8 row elements >= T -> all global top-8 >= T, cnt >= 8.
            float m8[8];
#pragma unroll
            for (int j = 0; j < 8; j++) m8[j] = s_max[tid + 32 * j];
            float T = 0.f;
#pragma unroll
            for (int r = 0; r < 8; r++) {
                float lv = m8[0]; int lj = 0;
#pragma unroll
                for (int j = 1; j < 8; j++) if (m8[j] > lv) { lv = m8[j]; lj = j; }
                float mv = warp_max(lv);
                unsigned ball = __ballot_sync(0xffffffffu, lv == mv);
                int wl = __ffs(ball) - 1;          // exactly one winner, even on ties
                if (tid == wl) m8[lj] = -INFINITY;
                T = mv;
            }
            if (tid == 0) s_T = T;
        } else if (tid < 64) {
            int j = tid - 32;  s_t[j]  = tgt[kbase + j];
        } else if (tid < 96) {
            int j = tid - 64;  s_d[j]  = dists[kbase + j];
        } else if (tid < 128) {
            int j = tid - 96;  s_lk[j] = logf(keyf[kbase + j]);
        } else if (tid < 160) {
            int j = tid - 128; s_ls[j] = logf(selp[kbase + j]);
        }
        __syncthreads();

        // ---- Main pass: single full DRAM read + zero-fill + rare candidate hits ----
        const float T = s_T;
        for (int base = tid; base < BATCH_END; base += NTHREADS * 4) {
            // 4 loads back-to-back (MLP=4), then 4 stores, then cheap checks
            float4 v0 = __ldcs(&in4[base]);
            float4 v1 = __ldcs(&in4[base +     NTHREADS]);
            float4 v2 = __ldcs(&in4[base + 2 * NTHREADS]);
            float4 v3 = __ldcs(&in4[base + 3 * NTHREADS]);
            __stcs(&out4[base],                z4);
            __stcs(&out4[base +     NTHREADS], z4);
            __stcs(&out4[base + 2 * NTHREADS], z4);
            __stcs(&out4[base + 3 * NTHREADS], z4);
            if (max4(v0) >= T) collect(v0, T, s_cand, &s_cnt_c);
            if (max4(v1) >= T) collect(v1, T, s_cand, &s_cnt_c);
            if (max4(v2) >= T) collect(v2, T, s_cand, &s_cnt_c);
            if (max4(v3) >= T) collect(v3, T, s_cand, &s_cnt_c);
        }
        for (int i = BATCH_END + tid; i < V4; i += NTHREADS) {   // tail: 832 float4s
            float4 v = __ldcs(&in4[i]);
            __stcs(&out4[i], z4);
            if (max4(v) >= T) collect(v, T, s_cand, &s_cnt_c);
        }
        __syncthreads();

        // ---- Exact top-8 from candidates (warp 0); serial fallback on overflow ----
        if (tid < 32) {
            int cnt = s_cnt_c;
            if (cnt <= CAND_CAP) {                 // normal path; cnt >= 8 guaranteed
                int per = (cnt + 31) / 32;         // disjoint lane subsets
#pragma unroll 1
                for (int r = 0; r < 8; r++) {
                    float lv = -INFINITY; int li = 0;
                    for (int e = 0; e < per; e++) {
                        int idx = tid + 32 * e;
                        if (idx < cnt) { float c = s_cand[idx]; if (c > lv) { lv = c; li = idx; } }
                    }
                    float mv = warp_max(lv);
                    unsigned ball = __ballot_sync(0xffffffffu, lv == mv);
                    int wl = __ffs(ball) - 1;      // one removal/round; ties land in
                    if (tid == wl) s_cand[li] = -INFINITY;  // consecutive rounds (= top_k)
                    if (tid == 0) s_top8[r] = mv;
                }
            } else if (tid == 0) {                 // overflow fallback: serial exact
                float t8[8];
#pragma unroll
                for (int j = 0; j < 8; j++) t8[j] = -1.0f;
                const float* rowp = nprobs + (size_t)row * Vdim;
                for (int i = 0; i < Vdim; i++) ins8(t8, rowp[i]);
#pragma unroll
                for (int j = 0; j < 8; j++) s_top8[j] = t8[j];
            }
        }
        __syncthreads();

        // ---- Phase C: per-row scalar math on warp 0 (one lane per k), smem-hot ----
        if (tid < Kdim) {
            const int k = tid;
            int   tv = s_t[k];
            float d  = s_d[k];
            float lk = s_lk[k];
            float ls = s_ls[k];

            // noise_logit: Linear(2->4) -> tanh -> Linear(4->1)
            float nz = b1b[0];
#pragma unroll
            for (int i = 0; i < 4; i++) {
                float h = tanhf(W1a[2 * i] * lk + W1a[2 * i + 1] * ls + b1a[i]);
                nz += W1b[i] * h;
            }

            // label_counts[k] = # distinct NONZERO labels in prefix [0..k]
            bool dup = false;
            for (int j = 0; j < k; j++) dup |= (s_t[j] == tv);
            int contrib = (tv != 0) && !dup;
            unsigned ball = __ballot_sync(0xffffffffu, contrib);
            unsigned lemask = 0xffffffffu >> (31 - k);
            s_cnt[k] = (float)__popc(ball & lemask);
            __syncwarp();

            // fc2 hidden unit k: tanh(W2a[k] . [dists(32), counts(32)] + b2a[k])
            float acc = b2a[k];
            const float* wrow = W2a + k * (2 * Kdim);
#pragma unroll
            for (int i = 0; i < Kdim; i++) acc += wrow[i] * s_d[i];
#pragma unroll
            for (int i = 0; i < Kdim; i++) acc += wrow[Kdim + i] * s_cnt[i];
            float h = tanhf(acc);

            // lambda_logit = W2b @ h + b2b
            float l0 = warp_sum(W2b[k] * h)        + b2b[0];
            float l1 = warp_sum(W2b[Kdim + k] * h) + b2b[1];

            // sim_lambda = W_func . [log(top8)(8), log_key(32), log_sel(32)] + b_func
            float part = Wf[8 + k] * lk + Wf[40 + k] * ls;
            if (k < 8) part += Wf[k] * logf(s_top8[k]);
            float sim = warp_sum(part) + bf[0];

            float lam   = 1.0f / (1.0f + expf(sim - l0));   // softmax([l0,sim])[0]
            float tempe = 1.0f / (1.0f + expf(-l1));        // sigmoid(l1)

            // probs = softmax(-dists*tempe + noise) over K
            float logit = -d * tempe + nz;
            float mx = warp_max(logit);
            float e  = expf(logit - mx);
            float se = warp_sum(e);
            s_p[k] = e / se;
            __syncwarp();

            if (k == 0) {
                out[(size_t)Vdim * ROWS + row] = lam;
                float* orow = out + (size_t)row * Vdim;
                for (int i = 0; i < Kdim; i++) orow[s_t[i]] = s_p[i];  // last-write-wins
            }
        }
        __syncthreads();   // protect smem reuse across row iterations
    }
}

extern "C" void kernel_launch(void* const* d_in, const int* in_sizes, int n_in,
                              void* d_out, int out_size) {
    const int*   tgt    = (const int*)  d_in[0];
    const float* dists  = (const float*)d_in[1];
    const float* keyf   = (const float*)d_in[2];
    const float* nprobs = (const float*)d_in[3];
    const float* selp   = (const float*)d_in[4];
    const float* Wf     = (const float*)d_in[5];
    const float* bf     = (const float*)d_in[6];
    const float* W1a    = (const float*)d_in[7];
    const float* b1a    = (const float*)d_in[8];
    const float* W1b    = (const float*)d_in[9];
    const float* b1b    = (const float*)d_in[10];
    const float* W2a    = (const float*)d_in[11];
    const float* b2a    = (const float*)d_in[12];
    const float* W2b    = (const float*)d_in[13];
    const float* b2b    = (const float*)d_in[14];
    float* out = (float*)d_out;

    robust_combiner_kernel<<<NBLOCKS, NTHREADS>>>(
        tgt, dists, keyf, nprobs, selp,
        Wf, bf, W1a, b1a, W1b, b1b, W2a, b2a, W2b, b2b, out);
}